// round 11
// baseline (speedup 1.0000x reference)
#include <cuda_runtime.h>
#include <cuda_bf16.h>
#include <cstdint>

#define HDIM  1024
#define BATCH 256
#define TLEN  512
#define NCTA  128
#define NTHR  512

// ---- dynamic smem layout (bytes) ----
#define RSB2   4160            // W row stride: 4096 + 64 -> conflict-free LDS.128
#define O_W2   0               // 32 * 4160 = 133120
#define O_P    133120          // float[8][64][36] = 73728
#define O_XS   206848          // float[64]
#define O_BIAS 207104          // float[32]
#define O_WIH  207232          // float[32]
#define O_WOUT 207360          // float[32]
#define O_RED  207488          // float[256]
#define SMEM_BYTES 208512

// h storage: packed uint32 (lo16=hi-bf16, hi16=lo-bf16), PAIR-PERMUTED within each
// 16-col block: slot(4t+0..3) = logical cols {2t, 2t+1, 2t+8, 2t+9}
__device__ __align__(16) uint32_t g_hpk[2][BATCH * HDIM];
__device__ float g_xp[2][BATCH][32];     // decoder partial dots
__device__ float g_out[BATCH * TLEN];
__device__ float g_feat[BATCH * 3];
__device__ float g_lossnum;
__device__ unsigned g_cntF;
__device__ unsigned g_relF;
__device__ unsigned g_cntG[4 * 32];      // 128B-padded per m-group
__device__ unsigned g_relG[4 * 32];

// -------- helpers --------
__device__ __forceinline__ uint32_t prmt(uint32_t a, uint32_t b, uint32_t s) {
    uint32_t d;
    asm("prmt.b32 %0, %1, %2, %3;" : "=r"(d) : "r"(a), "r"(b), "r"(s));
    return d;
}
__device__ __forceinline__ void mma_bf16(float c[4], uint32_t a0, uint32_t a1,
                                         uint32_t a2, uint32_t a3,
                                         uint32_t b0, uint32_t b1) {
    asm volatile(
        "mma.sync.aligned.m16n8k16.row.col.f32.bf16.bf16.f32 "
        "{%0,%1,%2,%3}, {%4,%5,%6,%7}, {%8,%9}, {%0,%1,%2,%3};"
        : "+f"(c[0]), "+f"(c[1]), "+f"(c[2]), "+f"(c[3])
        : "r"(a0), "r"(a1), "r"(a2), "r"(a3), "r"(b0), "r"(b1));
}
__device__ __forceinline__ uint32_t packsplit(float v) {
    __nv_bfloat16 hi = __float2bfloat16(v);
    __nv_bfloat16 lo = __float2bfloat16(v - __bfloat162float(hi));
    return (uint32_t)__bfloat16_as_ushort(hi) | ((uint32_t)__bfloat16_as_ushort(lo) << 16);
}
__device__ __forceinline__ float unpacksum(uint32_t w) {
    return __bfloat162float(__ushort_as_bfloat16((unsigned short)(w & 0xffffu))) +
           __bfloat162float(__ushort_as_bfloat16((unsigned short)(w >> 16)));
}
__device__ __forceinline__ float ftanh(float x) {
    float xc = fminf(fmaxf(x, -10.f), 10.f);
    float e = __expf(2.0f * xc);
    return __fdividef(e - 1.0f, e + 1.0f);
}
__device__ __forceinline__ int permslot(int p) {
    return 4 * ((p & 7) >> 1) + 2 * ((p >> 3) & 1) + (p & 1);
}
__device__ __forceinline__ unsigned ld_acq(const unsigned* p) {
    unsigned v;
    asm volatile("ld.global.acquire.gpu.u32 %0, [%1];" : "=r"(v) : "l"(p) : "memory");
    return v;
}
__device__ __forceinline__ void st_rel(unsigned* p, unsigned v) {
    asm volatile("st.global.release.gpu.u32 [%0], %1;" :: "l"(p), "r"(v) : "memory");
}

// -------- barrier: acq_rel atom arrive + acquire poll (monotonic, replay-safe) --------
__device__ __forceinline__ void gbar(unsigned* cnt, unsigned* rel, unsigned n, unsigned& ep) {
    __syncthreads();
    if (threadIdx.x == 0) {
        ep++;
        unsigned old;
        asm volatile("atom.global.add.acq_rel.gpu.u32 %0, [%1], 1;"
                     : "=r"(old) : "l"(cnt) : "memory");
        if (old == ep * n - 1u) {
            st_rel(rel, ep);
        } else {
            while ((int)(ld_acq(rel) - ep) < 0) { }
        }
    }
    __syncthreads();
}

extern "C" __global__ void __launch_bounds__(NTHR, 1) persist_mma(
    const float* __restrict__ input, const int* __restrict__ seqlen,
    const float* __restrict__ Wih_e, const float* __restrict__ Whh_e,
    const float* __restrict__ bih_e, const float* __restrict__ bhh_e,
    const float* __restrict__ Wenc,  const float* __restrict__ benc,
    const float* __restrict__ Wdec,  const float* __restrict__ bdec,
    const float* __restrict__ Wih_d, const float* __restrict__ Whh_d,
    const float* __restrict__ bih_d, const float* __restrict__ bhh_d,
    const float* __restrict__ Wout,  const float* __restrict__ bout,
    float* __restrict__ dout, int out_size)
{
    extern __shared__ __align__(16) char sc[];
    float* Psm     = (float*)(sc + O_P);
    float* xs      = (float*)(sc + O_XS);
    float* bias_sh = (float*)(sc + O_BIAS);
    float* wih_sh  = (float*)(sc + O_WIH);
    float* wout_sh = (float*)(sc + O_WOUT);
    float* red_f   = (float*)(sc + O_RED);

    const int tid  = threadIdx.x;
    const int wid  = tid >> 5;
    const int lane = tid & 31;
    const int g    = lane >> 2;
    const int tg   = lane & 3;
    const int kw   = wid & 7;       // K-split 0..7 (128 each)
    const int wq   = wid >> 3;      // m-half 0..1 (32 rows each)
    const int bx   = blockIdx.x;
    const int nt   = bx & 31;
    const int mt   = bx >> 5;
    const int n0   = nt * 32;
    const int m0   = mt * 64;
    const float bout0 = bout[0];

    unsigned epF = g_relF;
    unsigned epG = g_relG[mt * 32];
    unsigned* cG = &g_cntG[mt * 32];
    unsigned* rG = &g_relG[mt * 32];

    // ---- init: zero h buf 0, loss ----
    {
        int gtid = bx * NTHR + tid;
        *(uint4*)(g_hpk[0] + gtid * 4) = make_uint4(0, 0, 0, 0);
        if (gtid == 0) g_lossnum = 0.f;
    }
    gbar(&g_cntF, &g_relF, NCTA, epF);

    // ================= two RNN phases =================
    for (int phase = 0; phase < 2; phase++) {
        const float* Whh = phase ? Whh_d : Whh_e;
        const float* Wih = phase ? Wih_d : Wih_e;
        const float* bih = phase ? bih_d : bih_e;
        const float* bhh = phase ? bhh_d : bhh_e;

        // ---- preload W slice: per (nn,k16) 64B block, lane tg uint4 =
        //      {hi(k+2tg,k+2tg+1), hi(k+2tg+8,+9), lo(...), lo(...)} ----
        for (int i = tid; i < 32 * HDIM; i += NTHR) {
            int nn = i >> 10, k = i & 1023;
            float w = Whh[(size_t)(n0 + nn) * HDIM + k];
            __nv_bfloat16 hi = __float2bfloat16(w);
            __nv_bfloat16 lo = __float2bfloat16(w - __bfloat162float(hi));
            int k16g = k >> 4, tgs = (k & 7) >> 1, half = (k >> 3) & 1, b = k & 1;
            char* base = sc + O_W2 + nn * RSB2 + k16g * 64 + tgs * 16 + half * 4 + b * 2;
            *(__nv_bfloat16*)base       = hi;
            *(__nv_bfloat16*)(base + 8) = lo;
        }
        if (tid < 32) {
            bias_sh[tid] = bih[n0 + tid] + bhh[n0 + tid];
            wih_sh[tid]  = Wih[n0 + tid];
            wout_sh[tid] = Wout[n0 + tid];
        }
        __syncthreads();

        for (int t = 0; t < TLEN; t++) {
            const int rp = t & 1;
            const uint4* hp4 = (const uint4*)g_hpk[rp];

            // ---- per-row scalar x (early: overlaps mainloop latency) ----
            if (tid < 64) {
                float xv = 0.f;
                int row = m0 + tid;
                if (phase == 0) {
                    xv = input[(size_t)row * TLEN + t];
                } else if (t > 0) {
                    const float4* xp = (const float4*)&g_xp[(t - 1) & 1][row][0];
                    float sx = 0.f;
#pragma unroll
                    for (int j = 0; j < 8; j++) {
                        float4 v = __ldcg(xp + j);
                        sx += (v.x + v.y) + (v.z + v.w);
                    }
                    xv = sx + bout0;
                    if (nt == 0) g_out[(size_t)row * TLEN + (t - 1)] = xv;
                }
                xs[tid] = xv;
            }

            // ---- MMA mainloop: warp m32 x n32 over K=128, double-buffered A ----
            float acc[2][4][4];
#pragma unroll
            for (int mi = 0; mi < 2; mi++)
#pragma unroll
                for (int nb = 0; nb < 4; nb++)
#pragma unroll
                    for (int q = 0; q < 4; q++) acc[mi][nb][q] = 0.f;

            const int r0 = m0 + wq * 32 + g;
            int b4[4];
#pragma unroll
            for (int j = 0; j < 4; j++)
                b4[j] = (((r0 + 8 * j) * HDIM + kw * 128) >> 2) + tg;

            uint4 A[2][4];
#pragma unroll
            for (int j = 0; j < 4; j++) A[0][j] = __ldcg(hp4 + b4[j]);

#pragma unroll
            for (int c = 0; c < 8; c++) {
                if (c < 7) {
#pragma unroll
                    for (int j = 0; j < 4; j++)
                        A[(c + 1) & 1][j] = __ldcg(hp4 + b4[j] + (c + 1) * 4);
                }
                const uint4* Ac = A[c & 1];
                uint32_t ah[2][4], al[2][4];
#pragma unroll
                for (int mi = 0; mi < 2; mi++) {
                    uint4 u = Ac[mi * 2], w = Ac[mi * 2 + 1];
                    ah[mi][0] = prmt(u.x, u.y, 0x5410); al[mi][0] = prmt(u.x, u.y, 0x7632);
                    ah[mi][1] = prmt(w.x, w.y, 0x5410); al[mi][1] = prmt(w.x, w.y, 0x7632);
                    ah[mi][2] = prmt(u.z, u.w, 0x5410); al[mi][2] = prmt(u.z, u.w, 0x7632);
                    ah[mi][3] = prmt(w.z, w.w, 0x5410); al[mi][3] = prmt(w.z, w.w, 0x7632);
                }
                const char* wrow = sc + O_W2 + (size_t)g * RSB2 + (kw * 8 + c) * 64 + tg * 16;
#pragma unroll
                for (int nb = 0; nb < 4; nb++) {
                    uint4 v = *(const uint4*)(wrow + (size_t)nb * 8 * RSB2);
#pragma unroll
                    for (int mi = 0; mi < 2; mi++) {
                        mma_bf16(acc[mi][nb], ah[mi][0], ah[mi][1], ah[mi][2], ah[mi][3], v.x, v.y);
                        mma_bf16(acc[mi][nb], ah[mi][0], ah[mi][1], ah[mi][2], ah[mi][3], v.z, v.w);
                        mma_bf16(acc[mi][nb], al[mi][0], al[mi][1], al[mi][2], al[mi][3], v.x, v.y);
                    }
                }
            }

            // ---- store k-split partials ----
#pragma unroll
            for (int mi = 0; mi < 2; mi++) {
                int mrow = wq * 32 + mi * 16 + g;
#pragma unroll
                for (int nb = 0; nb < 4; nb++) {
                    int col = nb * 8 + tg * 2;
                    *(float2*)&Psm[(kw * 64 + mrow) * 36 + col]     = make_float2(acc[mi][nb][0], acc[mi][nb][1]);
                    *(float2*)&Psm[(kw * 64 + mrow + 8) * 36 + col] = make_float2(acc[mi][nb][2], acc[mi][nb][3]);
                }
            }
            __syncthreads();

            // ---- epilogue: reduce 8 partials, bias + x*Wih, tanh, pack, permuted store ----
            {
                int m = tid >> 3, c4 = (tid & 7) * 4;
                float s0 = 0.f, s1 = 0.f, s2 = 0.f, s3 = 0.f;
#pragma unroll
                for (int kwi = 0; kwi < 8; kwi++) {
                    float4 q = *(const float4*)&Psm[(kwi * 64 + m) * 36 + c4];
                    s0 += q.x; s1 += q.y; s2 += q.z; s3 += q.w;
                }
                float xv = xs[m];
                float hv[4];
                hv[0] = ftanh(s0 + bias_sh[c4]     + xv * wih_sh[c4]);
                hv[1] = ftanh(s1 + bias_sh[c4 + 1] + xv * wih_sh[c4 + 1]);
                hv[2] = ftanh(s2 + bias_sh[c4 + 2] + xv * wih_sh[c4 + 2]);
                hv[3] = ftanh(s3 + bias_sh[c4 + 3] + xv * wih_sh[c4 + 3]);
                uint32_t* dst = g_hpk[rp ^ 1] + (size_t)(m0 + m) * HDIM + n0 + (c4 & ~15);
                int sA = permslot(c4 & 15), sB = permslot((c4 + 2) & 15);
                *(uint2*)(dst + sA) = make_uint2(packsplit(hv[0]), packsplit(hv[1]));
                *(uint2*)(dst + sB) = make_uint2(packsplit(hv[2]), packsplit(hv[3]));
                if (phase == 1) {
                    float po = hv[0] * wout_sh[c4]     + hv[1] * wout_sh[c4 + 1]
                             + hv[2] * wout_sh[c4 + 2] + hv[3] * wout_sh[c4 + 3];
                    po += __shfl_xor_sync(0xffffffffu, po, 1);
                    po += __shfl_xor_sync(0xffffffffu, po, 2);
                    po += __shfl_xor_sync(0xffffffffu, po, 4);
                    if ((tid & 7) == 0) g_xp[t & 1][m0 + m][nt] = po;
                }
            }
            gbar(cG, rG, 32, epG);    // group-local barrier
        } // t  (final h in buf 0)

        gbar(&g_cntF, &g_relF, NCTA, epF);

        if (phase == 0) {
            // ---- features = sigmoid(hT @ Wenc^T + benc)  (permutation-aware) ----
            int d = bx * 16 + wid;
            if (d < 768) {
                int b = d / 3, e = d - 3 * b;
                const uint32_t* hpk = g_hpk[0] + (size_t)b * HDIM;
                const float* wp = Wenc + (size_t)e * HDIM;
                float s = 0.f;
                for (int k = lane * 4; k < HDIM; k += 128) {
                    uint4 w4 = __ldcg((const uint4*)(hpk + k));
                    int bk = k & ~15, t2 = (k >> 2) & 3;
                    s = fmaf(unpacksum(w4.x), wp[bk + 2 * t2],     s);
                    s = fmaf(unpacksum(w4.y), wp[bk + 2 * t2 + 1], s);
                    s = fmaf(unpacksum(w4.z), wp[bk + 2 * t2 + 8], s);
                    s = fmaf(unpacksum(w4.w), wp[bk + 2 * t2 + 9], s);
                }
#pragma unroll
                for (int o = 16; o; o >>= 1) s += __shfl_xor_sync(0xffffffffu, s, o);
                if (lane == 0) g_feat[b * 3 + e] = 1.f / (1.f + __expf(-(s + benc[e])));
            }
            gbar(&g_cntF, &g_relF, NCTA, epF);
            // ---- h0 = features @ Wdec^T + bdec -> buf 0 packed (permuted) ----
#pragma unroll
            for (int r = 0; r < 4; r++) {
                int i = bx * 2048 + r * NTHR + tid;
                int b = i >> 10, j = i & 1023;
                float v = bdec[j] + __ldcg(&g_feat[b * 3])     * Wdec[j * 3]
                                  + __ldcg(&g_feat[b * 3 + 1]) * Wdec[j * 3 + 1]
                                  + __ldcg(&g_feat[b * 3 + 2]) * Wdec[j * 3 + 2];
                g_hpk[0][((size_t)b << 10) | (j & ~15) | permslot(j & 15)] = packsplit(v);
            }
            gbar(&g_cntF, &g_relF, NCTA, epF);
        }
    } // phases

    // ---- tail: out[:, 511] = bout + sum xp[1] ----
    if (bx == 0 && tid < 256) {
        const float4* xp = (const float4*)&g_xp[1][tid][0];
        float s = bout0;
#pragma unroll
        for (int j = 0; j < 8; j++) {
            float4 v = __ldcg(xp + j);
            s += (v.x + v.y) + (v.z + v.w);
        }
        g_out[(size_t)tid * TLEN + (TLEN - 1)] = s;
    }
    gbar(&g_cntF, &g_relF, NCTA, epF);

    // ---- masked MSE numerator: 2 rows per CTA ----
    {
        int b = bx * 2 + (tid >> 8), l = tid & 255;
        int L = seqlen[b];
        float s = 0.f;
        for (int tt = l; tt < L; tt += 256) {
            float d = input[(size_t)b * TLEN + tt] - __ldcg(&g_out[(size_t)b * TLEN + tt]);
            s = fmaf(d, d, s);
        }
#pragma unroll
        for (int o = 16; o; o >>= 1) s += __shfl_xor_sync(0xffffffffu, s, o);
        if ((tid & 31) == 0) red_f[wid] = s;
        __syncthreads();
        if (tid == 0) {
            float tot = 0.f;
#pragma unroll
            for (int q = 0; q < 16; q++) tot += red_f[q];
            atomicAdd(&g_lossnum, tot);
        }
        __syncthreads();
    }
    gbar(&g_cntF, &g_relF, NCTA, epF);

    // ---- finalize loss (CTA 0) ----
    if (bx == 0) {
        if (tid < 256) red_f[tid] = (float)seqlen[tid];
        __syncthreads();
        for (int o = 128; o; o >>= 1) {
            if (tid < o && tid + o < 256) red_f[tid] += red_f[tid + o];
            __syncthreads();
        }
        if (tid == 0 && out_size > 0) dout[0] = g_lossnum / red_f[0];
    }

    // ---- pack (loss | input | output | features) ----
    {
        int chunk = (out_size + NCTA - 1) / NCTA;
        int lo = bx * chunk;
        int hi = lo + chunk; if (hi > out_size) hi = out_size;
        for (int i = lo + tid; i < hi; i += NTHR) {
            if (i == 0) continue;
            int j = i - 1;
            if (j < BATCH * TLEN) { dout[i] = input[j]; continue; }
            j -= BATCH * TLEN;
            if (j < BATCH * TLEN) { dout[i] = __ldcg(&g_out[j]); continue; }
            j -= BATCH * TLEN;
            if (j < BATCH * 3) { dout[i] = __ldcg(&g_feat[j]); continue; }
            dout[i] = 0.f;
        }
    }
}

extern "C" void kernel_launch(void* const* d_in, const int* in_sizes, int n_in,
                              void* d_out, int out_size) {
    const float* input  = (const float*)d_in[0];
    const int*   seqlen = (const int*)d_in[1];
    const float* Wih_e = (const float*)d_in[2];
    const float* Whh_e = (const float*)d_in[3];
    const float* bih_e = (const float*)d_in[4];
    const float* bhh_e = (const float*)d_in[5];
    const float* Wenc  = (const float*)d_in[6];
    const float* benc  = (const float*)d_in[7];
    const float* Wdec  = (const float*)d_in[8];
    const float* bdec  = (const float*)d_in[9];
    const float* Wih_d = (const float*)d_in[10];
    const float* Whh_d = (const float*)d_in[11];
    const float* bih_d = (const float*)d_in[12];
    const float* bhh_d = (const float*)d_in[13];
    const float* Wout  = (const float*)d_in[14];
    const float* bout  = (const float*)d_in[15];

    cudaFuncSetAttribute(persist_mma,
                         cudaFuncAttributeMaxDynamicSharedMemorySize, SMEM_BYTES);
    persist_mma<<<NCTA, NTHR, SMEM_BYTES>>>(
        input, seqlen, Wih_e, Whh_e, bih_e, bhh_e, Wenc, benc,
        Wdec, bdec, Wih_d, Whh_d, bih_d, bhh_d, Wout, bout,
        (float*)d_out, out_size);
}